// round 17
// baseline (speedup 1.0000x reference)
#include <cuda_runtime.h>
#include <cuda_bf16.h>

// Problem constants (fixed by the dataset): B=256, T=512, K=128
#define Bn 256
#define Tn 512
#define Kn 128
#define NSOLO 40          // solo CTAs (longest batches), 1 batch each
#define NCTA  148         // 40 solo + 108 pair CTAs = all SMs

// Device scratch (no allocs allowed).
__device__ float g_partial[Bn];
__device__ int   g_perm[Bn];   // g_perm[rank] = batch index, ascending length
__device__ int   g_done;       // zero-init; last CTA resets to 0 each run

// ---- scheduler: grid=32 x 256 threads; warp w ranks batch 8*bx+w ----------
__global__ void crf_sched_kernel(const int* __restrict__ seq_lens)
{
    const int lane = threadIdx.x & 31;
    const int i    = blockIdx.x * 8 + (threadIdx.x >> 5);
    const int Li   = seq_lens[i];
    int r = 0;
    #pragma unroll
    for (int kk = 0; kk < 8; kk++) {
        int k  = lane + 32 * kk;
        int Lk = seq_lens[k];
        r += (Lk < Li) || (Lk == Li && k < i);   // unique ranks
    }
    #pragma unroll
    for (int o = 16; o; o >>= 1) r += __shfl_xor_sync(0xffffffffu, r, o);
    if (lane == 0) g_perm[r] = i;
}

__device__ __forceinline__ float frcp(float x) {
    float q; asm("rcp.approx.f32 %0, %1;" : "=f"(q) : "f"(x));
    return q;
}

// Beta layout (bf16): half0 @ elements [0,64), half1 @ [72,136) (144-byte
// base offset -> the two half base addresses hit disjoint bank quads;
// conflict-free 2-address LDS.128 broadcast). Same for shF and shB.
#define HOFF 72
#define BSLOT(j) (((j) < 64) ? (j) : ((j) + 8))

// Fused fwd+bwd step on ALL 8 warps. Thread (j=tau>>1, h=tau&1) computes the
// i-half h of BOTH chains: 16 LDS.128 + 64 HFMA2 + one packed bf16x2 shuffle
// (F and B partials ride together); h=0 stores fwd beta[j], h=1 stores bwd
// z[j]. cj: each thread inlines ONE exp from its prefetched logit (its own
// chain's stream). Renorm (1-in-4) rescales each chain by rcp of its elem 0;
// S accumulates logf -> exact LSE shift per chain. LASTF_ makes the fwd
// multiplier 1 (the q_m step of the split identity); with REN_ it composes
// to rcp(r) exactly as R16 did.
#define FSTEP(REN_, LASTF_, LREG_, NEXTROW_) do {                            \
    float cj_ = __expf(LREG_);                                               \
    LREG_ = (NEXTROW_);                       /* refill raw prefetch */      \
    if ((LASTF_) && !h) cj_ = 1.f;                                           \
    if (REN_) {                                                              \
        float rr_ = __bfloat162float(h ? shB[curB][0] : shF[curF][0]);       \
        S += __logf(rr_);                                                    \
        cj_ *= frcp(rr_);                                                    \
    }                                                                        \
    const uint4* apF_ =                                                      \
        (const uint4*)((const __nv_bfloat16*)shF[curF] + HOFF * h);          \
    const uint4* apB_ =                                                      \
        (const uint4*)((const __nv_bfloat16*)shB[curB] + HOFF * h);          \
    __nv_bfloat162 f0_=zero2,f1_=zero2,f2_=zero2,f3_=zero2;                  \
    __nv_bfloat162 b0_=zero2,b1_=zero2,b2_=zero2,b3_=zero2;                  \
    _Pragma("unroll")                                                        \
    for (int k_ = 0; k_ < 8; k_++) {                                         \
        uint4 vF_ = apF_[k_];                /* LDS.128 broadcast */         \
        uint4 vB_ = apB_[k_];                                                \
        f0_ = __hfma2(*(__nv_bfloat162*)&vF_.x, eTf[4*k_+0], f0_);           \
        f1_ = __hfma2(*(__nv_bfloat162*)&vF_.y, eTf[4*k_+1], f1_);           \
        f2_ = __hfma2(*(__nv_bfloat162*)&vF_.z, eTf[4*k_+2], f2_);           \
        f3_ = __hfma2(*(__nv_bfloat162*)&vF_.w, eTf[4*k_+3], f3_);           \
        b0_ = __hfma2(*(__nv_bfloat162*)&vB_.x, eTb[4*k_+0], b0_);           \
        b1_ = __hfma2(*(__nv_bfloat162*)&vB_.y, eTb[4*k_+1], b1_);           \
        b2_ = __hfma2(*(__nv_bfloat162*)&vB_.z, eTb[4*k_+2], b2_);           \
        b3_ = __hfma2(*(__nv_bfloat162*)&vB_.w, eTb[4*k_+3], b3_);           \
    }                                                                        \
    __nv_bfloat162 sF_ = __hadd2(__hadd2(f0_, f1_), __hadd2(f2_, f3_));      \
    sF_ = __hadd2(sF_, __lowhigh2highlow(sF_));                              \
    __nv_bfloat162 sB_ = __hadd2(__hadd2(b0_, b1_), __hadd2(b2_, b3_));      \
    sB_ = __hadd2(sB_, __lowhigh2highlow(sB_));                              \
    __nv_bfloat162 pk_; pk_.x = sF_.x; pk_.y = sB_.x;                        \
    unsigned pu_ = __shfl_xor_sync(0xffffffffu, *(unsigned*)&pk_, 1);        \
    __nv_bfloat162 tot_ = __hadd2(pk_, *(__nv_bfloat162*)&pu_);              \
    float mine_ = __bfloat162float(h ? tot_.y : tot_.x) * cj_;               \
    if (h) shB[curB ^ 1][slotj] = __float2bfloat16(mine_);                   \
    else   shF[curF ^ 1][slotj] = __float2bfloat16(mine_);                   \
    __syncthreads();                          /* the ONLY barrier/step */    \
    curF ^= 1; curB ^= 1;                                                    \
} while (0)

// Extra forward-only step when (Tlen-1) is odd: cj = 1, no renorm.
#define FWD1() do {                                                          \
    const uint4* apF_ =                                                      \
        (const uint4*)((const __nv_bfloat16*)shF[curF] + HOFF * h);          \
    __nv_bfloat162 f0_=zero2,f1_=zero2,f2_=zero2,f3_=zero2;                  \
    _Pragma("unroll")                                                        \
    for (int k_ = 0; k_ < 8; k_++) {                                         \
        uint4 vF_ = apF_[k_];                                                \
        f0_ = __hfma2(*(__nv_bfloat162*)&vF_.x, eTf[4*k_+0], f0_);           \
        f1_ = __hfma2(*(__nv_bfloat162*)&vF_.y, eTf[4*k_+1], f1_);           \
        f2_ = __hfma2(*(__nv_bfloat162*)&vF_.z, eTf[4*k_+2], f2_);           \
        f3_ = __hfma2(*(__nv_bfloat162*)&vF_.w, eTf[4*k_+3], f3_);           \
    }                                                                        \
    __nv_bfloat162 sF_ = __hadd2(__hadd2(f0_, f1_), __hadd2(f2_, f3_));      \
    sF_ = __hadd2(sF_, __lowhigh2highlow(sF_));                              \
    unsigned pu_ = __shfl_xor_sync(0xffffffffu, *(unsigned*)&sF_, 1);        \
    __nv_bfloat162 tot_ = __hadd2(sF_, *(__nv_bfloat162*)&pu_);              \
    if (!h) shF[curF ^ 1][slotj] = tot_.x;                                   \
    __syncthreads();                                                         \
    curF ^= 1;                                                               \
} while (0)

// Hybrid schedule over 148 SMs; every batch fwd/bwd split in one CTA:
//   CTAs 0..39   : 1 batch,  perm[255-c]           -> ~(L/2) fused steps
//   CTAs 40..147 : 2 batches perm[k], perm[215-k]  -> ~(L1+L2)/2 fused steps
__global__ __launch_bounds__(256, 1) void crf_forward_kernel(
    const float* __restrict__ logits,   // [B, T, K]
    const int*   __restrict__ labels,   // [B, T]
    const int*   __restrict__ seq_lens, // [B]
    const float* __restrict__ trans,    // [K, K] trans[i*K + j]
    float* __restrict__ out)
{
    __shared__ __align__(16) __nv_bfloat16 shF[2][144];
    __shared__ __align__(16) __nv_bfloat16 shB[2][144];
    __shared__ float sh_wred[8];
    __shared__ float sh_s[2];            // Sf, Sb
    __shared__ int   sh_last;

    const int c    = blockIdx.x;          // 0..147
    const int tau  = threadIdx.x;         // 0..255
    const int j    = tau >> 1;            // column/row 0..127
    const int h    = tau & 1;             // summation half (both chains)
    const int lane = tau & 31;
    const int warp = tau >> 5;
    const int slotj = BSLOT(j);

    const bool solo = (c < NSOLO);
    const int  nb   = solo ? 1 : 2;
    const int  r0   = solo ? ((Bn - 1) - c) : (c - NSOLO);
    const int  r1   = 215 - (c - NSOLO);

    const __nv_bfloat162 zero2 = __float2bfloat162_rn(0.f);

    // eTf[k]: expT col j, rows 64h+2k,+1.  eTb[k]: expT row j, cols 64h+2k,+1.
    __nv_bfloat162 eTf[32], eTb[32];
    #pragma unroll
    for (int k = 0; k < 32; k++) {
        float e0 = __expf(trans[(64 * h + 2 * k)     * Kn + j]);  // coalesced
        float e1 = __expf(trans[(64 * h + 2 * k + 1) * Kn + j]);
        eTf[k] = __floats2bfloat162_rn(e0, e1);
        float q0 = __expf(trans[j * Kn + 64 * h + 2 * k]);
        float q1 = __expf(trans[j * Kn + 64 * h + 2 * k + 1]);
        eTb[k] = __floats2bfloat162_rn(q0, q1);
    }

    for (int p = 0; p < nb; p++) {
        const int b = g_perm[p ? r1 : r0];
        const int    Tlen = seq_lens[b];                  // 1..512
        const float* lg   = logits + (size_t)b * Tn * Kn;
        const int*   lb   = labels + b * Tn;

        // ---------- gold-path score: unary + pairwise (fp32 exact) --------
        float sc = 0.f;
        for (int t = tau; t < Tlen; t += 256) {
            int y = lb[t];
            sc += lg[t * Kn + y];
            if (t >= 1) sc += trans[lb[t - 1] * Kn + y];
        }
        #pragma unroll
        for (int o = 16; o; o >>= 1) sc += __shfl_xor_sync(0xffffffffu, sc, o);
        if (lane == 0) sh_wred[warp] = sc;

        // my multiplier-stream row for fused step ss: h=0 -> ss, h=1 -> T-1-ss
        #define QROW(ss) lg[(h ? (((Tlen - 1 - (ss)) > 0) ? (Tlen - 1 - (ss)) : 0) \
                               : ((((ss) < Tn) ? (ss) : (Tn - 1)))) * Kn + j]
        // Prologue seeds: shF = c_0; shB = c_{T-1} (or 1 if T==1).
        if (!h) {
            shF[0][slotj] = __float2bfloat16(__expf(lg[j]));
        } else {
            shB[0][slotj] = (Tlen == 1) ? __float2bfloat16(1.f)
                          : __float2bfloat16(__expf(lg[(Tlen - 1) * Kn + j]));
        }
        // raw prefetch: my stream's rows for fused steps 1..4
        float l0 = QROW(1), l1 = QROW(2), l2 = QROW(3), l3 = QROW(4);

        __syncthreads();
        float score = 0.f;
        #pragma unroll
        for (int w = 0; w < 8; w++) score += sh_wred[w];

        // ---------- fused fwd+bwd recursion, 4x unrolled, renorm 1-in-4 ---
        const int nsteps = Tlen - 1;
        const int F      = nsteps >> 1;       // fused steps
        const int odd    = nsteps & 1;        // extra fwd-only (cj=1) step
        float S = 0.f;                        // Sf on h=0 threads, Sb on h=1
        int curF = 0, curB = 0;
        int s = 1;
        while (s + 3 <= F) {
            FSTEP(true,  false, l0, QROW(s + 4));
            FSTEP(false, false, l1, QROW(s + 5));
            FSTEP(false, false, l2, QROW(s + 6));
            FSTEP(false, ((s + 3 == F) && !odd), l3, QROW(s + 7));
            s += 4;
        }
        // remainder fused steps (<=3); l0..l2 hold the needed rows
        if (s     <= F) FSTEP(true,  ((s     == F) && !odd), l0, 0.f);
        if (s + 1 <= F) FSTEP(false, ((s + 1 == F) && !odd), l1, 0.f);
        if (s + 2 <= F) FSTEP(false, ((s + 2 == F) && !odd), l2, 0.f);
        if (odd) FWD1();                      // q_m step when nsteps is odd
        #undef QROW

        // ---------- log_z = Sf + Sb + log(dot(shF, shB)) ------------------
        float v = 0.f;
        if (tau < Kn) {
            int sl = BSLOT(tau);
            v = __bfloat162float(shF[curF][sl]) *
                __bfloat162float(shB[curB][sl]);
        }
        #pragma unroll
        for (int o = 16; o; o >>= 1) v += __shfl_xor_sync(0xffffffffu, v, o);
        if (lane == 0) sh_wred[warp] = v;
        if (tau < 2) sh_s[tau] = S;           // tau0: Sf, tau1: Sb
        __syncthreads();

        if (tau == 0) {
            float dot = ((sh_wred[0] + sh_wred[1]) + (sh_wred[2] + sh_wred[3]))
                      + ((sh_wred[4] + sh_wred[5]) + (sh_wred[6] + sh_wred[7]));
            g_partial[b] = sh_s[0] + sh_s[1] + __logf(dot) - score;
        }
        __syncthreads();                     // smem safe for next batch
    }

    // ---------- fused final reduction: last CTA sums deterministically ----
    if (tau == 0) {
        __threadfence();
        int d = atomicAdd(&g_done, 1);
        sh_last = (d == (NCTA - 1));
    }
    __syncthreads();
    if (sh_last) {
        __threadfence();                 // see all CTAs' g_partial writes
        float w = g_partial[tau];        // fixed-tree: deterministic
        #pragma unroll
        for (int o = 16; o; o >>= 1) w += __shfl_xor_sync(0xffffffffu, w, o);
        if (lane == 0) sh_wred[warp] = w;
        __syncthreads();
        if (tau == 0) {
            float s2 = ((sh_wred[0] + sh_wred[1]) + (sh_wred[2] + sh_wred[3]))
                     + ((sh_wred[4] + sh_wred[5]) + (sh_wred[6] + sh_wred[7]));
            out[0]  = s2;
            g_done  = 0;                 // reset for next graph replay
        }
    }
}

extern "C" void kernel_launch(void* const* d_in, const int* in_sizes, int n_in,
                              void* d_out, int out_size)
{
    const float* logits   = (const float*)d_in[0];
    const int*   labels   = (const int*)  d_in[1];
    const int*   seq_lens = (const int*)  d_in[2];
    const float* trans    = (const float*)d_in[3];
    float*       out      = (float*)d_out;

    crf_sched_kernel<<<32, 256>>>(seq_lens);
    crf_forward_kernel<<<NCTA, 256>>>(logits, labels, seq_lens, trans, out);
}